// round 1
// baseline (speedup 1.0000x reference)
#include <cuda_runtime.h>
#include <math.h>

#define CAP 32768
#define NB  32
#define CD  64
#define TOPK 16

// ---------------- scratch (no allocations allowed) ----------------
__device__ float g_qpart[NB * CD];        // q@W1[:64] + b1, [b][h]
__device__ float g_qn[NB * CD];           // normalized query_context, [b][h]
__device__ float g_mpart[CAP * CD];       // memory_content @ W1[64:], [c][h]
__device__ float g_invnorm[CAP];          // 1/max(||mctx[c]||, eps)
__device__ float g_scores[NB * CAP];      // final scores, [b][c]

// ---------------- K0: query-side prep ----------------
__global__ __launch_bounds__(256) void k0_prep(
    const float* __restrict__ qc, const float* __restrict__ qctx,
    const float* __restrict__ W1, const float* __restrict__ b1)
{
    int tid = threadIdx.x;
    // q_part[b][h] = b1[h] + sum_d qc[b][d] * W1[d][h]
    for (int idx = tid; idx < NB * CD; idx += 256) {
        int b = idx >> 6, h = idx & 63;
        float s = b1[h];
        #pragma unroll 8
        for (int d = 0; d < CD; d++)
            s = fmaf(qc[b * CD + d], W1[d * CD + h], s);
        g_qpart[idx] = s;
    }
    // qn[b][:] = qctx[b]/max(||qctx[b]||, eps)   (warp per row, 4 rows/warp)
    int w = tid >> 5, lane = tid & 31;
    for (int j = 0; j < 4; j++) {
        int b = w + j * 8;
        float v0 = qctx[b * CD + lane];
        float v1 = qctx[b * CD + 32 + lane];
        float ss = v0 * v0 + v1 * v1;
        #pragma unroll
        for (int o = 16; o; o >>= 1) ss += __shfl_xor_sync(0xFFFFFFFFu, ss, o);
        float inv = 1.0f / fmaxf(sqrtf(ss), 1e-8f);
        g_qn[b * CD + lane]      = v0 * inv;
        g_qn[b * CD + 32 + lane] = v1 * inv;
    }
}

// ---------------- K1: m_part GEMM + mctx inv-norms ----------------
// block: 256 threads, 128 memory rows. smem: A tile 32KB + W1b 16KB = 48KB.
__global__ __launch_bounds__(256) void k1_mpart(
    const float* __restrict__ mc, const float* __restrict__ mctx,
    const float* __restrict__ W1)
{
    __shared__ float sA[128 * 64];
    __shared__ float sB[64 * 64];
    int tid = threadIdx.x;
    int rowbase = blockIdx.x * 128;

    // load W1 bottom half [64][64] (rows 64..127 of W1)
    {
        const float4* src = (const float4*)(W1 + 64 * 64);
        float4* dst = (float4*)sB;
        for (int i = tid; i < 1024; i += 256) dst[i] = src[i];
    }
    // load A tile [128][64]
    {
        const float4* src = (const float4*)(mc + (size_t)rowbase * CD);
        float4* dst = (float4*)sA;
        for (int i = tid; i < 2048; i += 256) dst[i] = src[i];
    }
    // mctx inv-norms: warp per row, 16 rows per warp
    {
        int w = tid >> 5, lane = tid & 31;
        for (int j = 0; j < 16; j++) {
            int c = rowbase + w * 16 + j;
            float v0 = mctx[c * CD + lane];
            float v1 = mctx[c * CD + 32 + lane];
            float ss = v0 * v0 + v1 * v1;
            #pragma unroll
            for (int o = 16; o; o >>= 1) ss += __shfl_xor_sync(0xFFFFFFFFu, ss, o);
            if (lane == 0) g_invnorm[c] = 1.0f / fmaxf(sqrtf(ss), 1e-8f);
        }
    }
    __syncthreads();

    // GEMM: thread computes 8 rows x 4 cols
    int r0 = (tid >> 4) * 8;
    int c0 = (tid & 15) * 4;
    float acc[8][4];
    #pragma unroll
    for (int i = 0; i < 8; i++)
        #pragma unroll
        for (int j = 0; j < 4; j++) acc[i][j] = 0.0f;

    #pragma unroll 4
    for (int d = 0; d < 64; d++) {
        float4 bv = *(const float4*)&sB[d * 64 + c0];
        #pragma unroll
        for (int i = 0; i < 8; i++) {
            float a = sA[(r0 + i) * 64 + d];
            acc[i][0] = fmaf(a, bv.x, acc[i][0]);
            acc[i][1] = fmaf(a, bv.y, acc[i][1]);
            acc[i][2] = fmaf(a, bv.z, acc[i][2]);
            acc[i][3] = fmaf(a, bv.w, acc[i][3]);
        }
    }
    #pragma unroll
    for (int i = 0; i < 8; i++) {
        float4 o = make_float4(acc[i][0], acc[i][1], acc[i][2], acc[i][3]);
        *(float4*)&g_mpart[(size_t)(rowbase + r0 + i) * CD + c0] = o;
    }
}

// ---------------- K2: scoring (hot kernel) ----------------
// warp per memory row, lane = query b. 16 rows per warp, processed in pairs.
__global__ __launch_bounds__(256, 1) void k2_score(
    const float* __restrict__ mctx, const float* __restrict__ fresh,
    const float* __restrict__ W2, const float* __restrict__ b2p)
{
    __shared__ float4 s_mp[8][2][16];
    __shared__ float4 s_mx[8][2][16];
    __shared__ float4 s_w2[16];

    int tid = threadIdx.x, w = tid >> 5, lane = tid & 31;
    if (tid < 16) s_w2[tid] = ((const float4*)W2)[tid];
    __syncthreads();

    float b2v = b2p[0];

    // q_part / qn for this lane's query, in registers
    float qp[64], qn[64];
    {
        const float4* a4 = (const float4*)(g_qpart + lane * CD);
        const float4* n4 = (const float4*)(g_qn + lane * CD);
        #pragma unroll
        for (int i = 0; i < 16; i++) {
            float4 a = a4[i];
            qp[4 * i + 0] = a.x; qp[4 * i + 1] = a.y; qp[4 * i + 2] = a.z; qp[4 * i + 3] = a.w;
            float4 n = n4[i];
            qn[4 * i + 0] = n.x; qn[4 * i + 1] = n.y; qn[4 * i + 2] = n.z; qn[4 * i + 3] = n.w;
        }
    }

    int wg = blockIdx.x * 8 + w;
    int base = wg * 16;           // 16 rows per warp
    int half = lane >> 4, q = lane & 15;

    float4 nmp = ((const float4*)(g_mpart + (size_t)(base + half) * CD))[q];
    float4 nmx = ((const float4*)(mctx + (size_t)(base + half) * CD))[q];

    #pragma unroll 1
    for (int p = 0; p < 8; p++) {
        int c0 = base + 2 * p;
        s_mp[w][half][q] = nmp;
        s_mx[w][half][q] = nmx;
        __syncwarp();
        if (p < 7) {
            nmp = ((const float4*)(g_mpart + (size_t)(c0 + 2 + half) * CD))[q];
            nmx = ((const float4*)(mctx + (size_t)(c0 + 2 + half) * CD))[q];
        }
        #pragma unroll
        for (int r = 0; r < 2; r++) {
            int c = c0 + r;
            float ac0 = 0.f, ac1 = 0.f, ac2 = 0.f, ac3 = 0.f;
            float ax0 = 0.f, ax1 = 0.f, ax2 = 0.f, ax3 = 0.f;
            #pragma unroll
            for (int i = 0; i < 16; i++) {
                float4 mp = s_mp[w][r][i];
                float4 mx = s_mx[w][r][i];
                float4 w2 = s_w2[i];
                float t0 = fmaxf(qp[4 * i + 0] + mp.x, 0.0f);
                float t1 = fmaxf(qp[4 * i + 1] + mp.y, 0.0f);
                float t2 = fmaxf(qp[4 * i + 2] + mp.z, 0.0f);
                float t3 = fmaxf(qp[4 * i + 3] + mp.w, 0.0f);
                ac0 = fmaf(t0, w2.x, ac0);
                ac1 = fmaf(t1, w2.y, ac1);
                ac2 = fmaf(t2, w2.z, ac2);
                ac3 = fmaf(t3, w2.w, ac3);
                ax0 = fmaf(qn[4 * i + 0], mx.x, ax0);
                ax1 = fmaf(qn[4 * i + 1], mx.y, ax1);
                ax2 = fmaf(qn[4 * i + 2], mx.z, ax2);
                ax3 = fmaf(qn[4 * i + 3], mx.w, ax3);
            }
            float z   = (ac0 + ac1) + (ac2 + ac3) + b2v;
            float ctx = ((ax0 + ax1) + (ax2 + ax3)) * g_invnorm[c];
            float sig = 1.0f / (1.0f + expf(-z));
            float score = 0.5f * sig + 0.3f * ctx + 0.2f * fresh[c];
            g_scores[lane * CAP + c] = score;
        }
        __syncwarp();
    }
}

// ---------------- K3: top-16 + gather ----------------
// one block per query b. chunk-max hierarchy (1024 chunks of 32).
__global__ __launch_bounds__(256) void k3_topk(
    const float* __restrict__ mc, const float* __restrict__ fresh,
    float* __restrict__ out)
{
    __shared__ float s_cmax[1024];
    __shared__ int   s_selidx[TOPK];
    __shared__ float s_selval[TOPK];

    int b = blockIdx.x;
    int tid = threadIdx.x;
    const float* sc = g_scores + (size_t)b * CAP;

    if (tid < TOPK) s_selidx[tid] = -1;

    for (int chunk = tid; chunk < 1024; chunk += 256) {
        const float4* p = (const float4*)(sc + chunk * 32);
        float m = -1e30f;
        #pragma unroll
        for (int j = 0; j < 8; j++) {
            float4 v = p[j];
            m = fmaxf(m, fmaxf(fmaxf(v.x, v.y), fmaxf(v.z, v.w)));
        }
        s_cmax[chunk] = m;
    }
    __syncthreads();

    if (tid < 32) {
        int lane = tid;
        for (int k = 0; k < TOPK; k++) {
            // argmax over chunk maxes (ties -> lowest chunk index)
            float bv = -1e30f; int bc = 0x7FFFFFFF;
            #pragma unroll 8
            for (int j = 0; j < 32; j++) {
                int ch = lane + j * 32;
                float v = s_cmax[ch];
                if (v > bv || (v == bv && ch < bc)) { bv = v; bc = ch; }
            }
            #pragma unroll
            for (int o = 16; o; o >>= 1) {
                float ov = __shfl_xor_sync(0xFFFFFFFFu, bv, o);
                int   oc = __shfl_xor_sync(0xFFFFFFFFu, bc, o);
                if (ov > bv || (ov == bv && oc < bc)) { bv = ov; bc = oc; }
            }
            // argmax inside the winning chunk, masking already-selected
            int c = bc * 32 + lane;
            float v = sc[c];
            for (int j = 0; j < TOPK; j++)
                if (j < k && c == s_selidx[j]) v = -1e30f;
            float ev = v; int bi = c;
            #pragma unroll
            for (int o = 16; o; o >>= 1) {
                float ov = __shfl_xor_sync(0xFFFFFFFFu, ev, o);
                int   oi = __shfl_xor_sync(0xFFFFFFFFu, bi, o);
                if (ov > ev || (ov == ev && oi < bi)) { ev = ov; bi = oi; }
            }
            // new chunk max excluding the element just selected
            float v2 = (c == bi) ? -1e30f : v;
            #pragma unroll
            for (int o = 16; o; o >>= 1)
                v2 = fmaxf(v2, __shfl_xor_sync(0xFFFFFFFFu, v2, o));
            if (lane == 0) {
                s_selidx[k] = bi;
                s_selval[k] = ev;
                s_cmax[bc] = v2;
            }
            __syncwarp();
        }
    }
    __syncthreads();

    // gather outputs: [content | top_similarities | retrieved_time_weights]
    for (int i = tid; i < TOPK * CD; i += 256) {
        int k = i >> 6, h = i & 63;
        out[(size_t)b * (TOPK * CD) + i] = mc[(size_t)s_selidx[k] * CD + h];
    }
    if (tid < TOPK) {
        out[NB * TOPK * CD + b * TOPK + tid] = s_selval[tid];
        out[NB * TOPK * CD + NB * TOPK + b * TOPK + tid] = fresh[s_selidx[tid]];
    }
}

// ---------------- launch ----------------
extern "C" void kernel_launch(void* const* d_in, const int* in_sizes, int n_in,
                              void* d_out, int out_size)
{
    const float* qc    = (const float*)d_in[0];
    const float* qctx  = (const float*)d_in[1];
    const float* mc    = (const float*)d_in[2];
    const float* mctx  = (const float*)d_in[3];
    const float* fresh = (const float*)d_in[4];
    const float* W1    = (const float*)d_in[5];
    const float* b1    = (const float*)d_in[6];
    const float* W2    = (const float*)d_in[7];
    const float* b2    = (const float*)d_in[8];
    float* out = (float*)d_out;

    k0_prep<<<1, 256>>>(qc, qctx, W1, b1);
    k1_mpart<<<CAP / 128, 256>>>(mc, mctx, W1);
    k2_score<<<CAP / (16 * 8), 256>>>(mctx, fresh, W2, b2);
    k3_topk<<<NB, 256>>>(mc, fresh, out);
}

// round 2
// speedup vs baseline: 1.1376x; 1.1376x over previous
#include <cuda_runtime.h>
#include <math.h>

#define CAP 32768
#define NB  32
#define CD  64
#define TOPK 16
#define NCHUNK 2048   // CAP/16 chunks of 16 per query row

// ---------------- scratch (no allocations allowed) ----------------
__device__ float g_qpart[NB * CD];        // q@W1[:64] + b1, [b][h]
__device__ float g_qn[NB * CD];           // normalized query_context, [b][h]
__device__ float g_mpart[CAP * CD];       // memory_content @ W1[64:], [c][h]
__device__ float g_invnorm[CAP];          // 1/max(||mctx[c]||, eps)
__device__ float g_scores[NB * CAP];      // final scores, [b][c]
__device__ float g_cmax[NB * NCHUNK];     // per-16-chunk maxes, [b][chunk]

// ---------------- K0: query-side prep ----------------
__global__ __launch_bounds__(256) void k0_prep(
    const float* __restrict__ qc, const float* __restrict__ qctx,
    const float* __restrict__ W1, const float* __restrict__ b1)
{
    int tid = threadIdx.x;
    for (int idx = tid; idx < NB * CD; idx += 256) {
        int b = idx >> 6, h = idx & 63;
        float s = b1[h];
        #pragma unroll 8
        for (int d = 0; d < CD; d++)
            s = fmaf(qc[b * CD + d], W1[d * CD + h], s);
        g_qpart[idx] = s;
    }
    int w = tid >> 5, lane = tid & 31;
    for (int j = 0; j < 4; j++) {
        int b = w + j * 8;
        float v0 = qctx[b * CD + lane];
        float v1 = qctx[b * CD + 32 + lane];
        float ss = v0 * v0 + v1 * v1;
        #pragma unroll
        for (int o = 16; o; o >>= 1) ss += __shfl_xor_sync(0xFFFFFFFFu, ss, o);
        float inv = 1.0f / fmaxf(sqrtf(ss), 1e-8f);
        g_qn[b * CD + lane]      = v0 * inv;
        g_qn[b * CD + 32 + lane] = v1 * inv;
    }
}

// ---------------- K1: m_part GEMM + mctx inv-norms ----------------
__global__ __launch_bounds__(256) void k1_mpart(
    const float* __restrict__ mc, const float* __restrict__ mctx,
    const float* __restrict__ W1)
{
    __shared__ float sA[128 * 64];
    __shared__ float sB[64 * 64];
    int tid = threadIdx.x;
    int rowbase = blockIdx.x * 128;

    {
        const float4* src = (const float4*)(W1 + 64 * 64);
        float4* dst = (float4*)sB;
        for (int i = tid; i < 1024; i += 256) dst[i] = src[i];
    }
    {
        const float4* src = (const float4*)(mc + (size_t)rowbase * CD);
        float4* dst = (float4*)sA;
        for (int i = tid; i < 2048; i += 256) dst[i] = src[i];
    }
    {
        int w = tid >> 5, lane = tid & 31;
        for (int j = 0; j < 16; j++) {
            int c = rowbase + w * 16 + j;
            float v0 = mctx[c * CD + lane];
            float v1 = mctx[c * CD + 32 + lane];
            float ss = v0 * v0 + v1 * v1;
            #pragma unroll
            for (int o = 16; o; o >>= 1) ss += __shfl_xor_sync(0xFFFFFFFFu, ss, o);
            if (lane == 0) g_invnorm[c] = 1.0f / fmaxf(sqrtf(ss), 1e-8f);
        }
    }
    __syncthreads();

    int r0 = (tid >> 4) * 8;
    int c0 = (tid & 15) * 4;
    float acc[8][4];
    #pragma unroll
    for (int i = 0; i < 8; i++)
        #pragma unroll
        for (int j = 0; j < 4; j++) acc[i][j] = 0.0f;

    #pragma unroll 2
    for (int d4 = 0; d4 < 16; d4++) {
        float4 bv0 = *(const float4*)&sB[(4 * d4 + 0) * 64 + c0];
        float4 bv1 = *(const float4*)&sB[(4 * d4 + 1) * 64 + c0];
        float4 bv2 = *(const float4*)&sB[(4 * d4 + 2) * 64 + c0];
        float4 bv3 = *(const float4*)&sB[(4 * d4 + 3) * 64 + c0];
        #pragma unroll
        for (int i = 0; i < 8; i++) {
            float4 a = *(const float4*)&sA[(r0 + i) * 64 + 4 * d4];
            acc[i][0] = fmaf(a.x, bv0.x, acc[i][0]);
            acc[i][1] = fmaf(a.x, bv0.y, acc[i][1]);
            acc[i][2] = fmaf(a.x, bv0.z, acc[i][2]);
            acc[i][3] = fmaf(a.x, bv0.w, acc[i][3]);
            acc[i][0] = fmaf(a.y, bv1.x, acc[i][0]);
            acc[i][1] = fmaf(a.y, bv1.y, acc[i][1]);
            acc[i][2] = fmaf(a.y, bv1.z, acc[i][2]);
            acc[i][3] = fmaf(a.y, bv1.w, acc[i][3]);
            acc[i][0] = fmaf(a.z, bv2.x, acc[i][0]);
            acc[i][1] = fmaf(a.z, bv2.y, acc[i][1]);
            acc[i][2] = fmaf(a.z, bv2.z, acc[i][2]);
            acc[i][3] = fmaf(a.z, bv2.w, acc[i][3]);
            acc[i][0] = fmaf(a.w, bv3.x, acc[i][0]);
            acc[i][1] = fmaf(a.w, bv3.y, acc[i][1]);
            acc[i][2] = fmaf(a.w, bv3.z, acc[i][2]);
            acc[i][3] = fmaf(a.w, bv3.w, acc[i][3]);
        }
    }
    #pragma unroll
    for (int i = 0; i < 8; i++) {
        float4 o = make_float4(acc[i][0], acc[i][1], acc[i][2], acc[i][3]);
        *(float4*)&g_mpart[(size_t)(rowbase + r0 + i) * CD + c0] = o;
    }
}

// ---------------- K2: scoring (hot kernel) ----------------
// warp per chunk of 16 memory rows, lane = query index b.
__global__ __launch_bounds__(256, 1) void k2_score(
    const float* __restrict__ mctx, const float* __restrict__ fresh,
    const float* __restrict__ W2, const float* __restrict__ b2p)
{
    __shared__ float4 s_mp[8][2][16];
    __shared__ float4 s_mx[8][2][16];
    __shared__ float4 s_w2[16];

    int tid = threadIdx.x, w = tid >> 5, lane = tid & 31;
    if (tid < 16) s_w2[tid] = ((const float4*)W2)[tid];
    __syncthreads();

    float b2v = b2p[0];

    float qp[64], qn[64];
    {
        const float4* a4 = (const float4*)(g_qpart + lane * CD);
        const float4* n4 = (const float4*)(g_qn + lane * CD);
        #pragma unroll
        for (int i = 0; i < 16; i++) {
            float4 a = a4[i];
            qp[4 * i + 0] = a.x; qp[4 * i + 1] = a.y; qp[4 * i + 2] = a.z; qp[4 * i + 3] = a.w;
            float4 n = n4[i];
            qn[4 * i + 0] = n.x; qn[4 * i + 1] = n.y; qn[4 * i + 2] = n.z; qn[4 * i + 3] = n.w;
        }
    }

    int wg = blockIdx.x * 8 + w;
    int base = wg * 16;
    int half = lane >> 4, q = lane & 15;

    float4 nmp = ((const float4*)(g_mpart + (size_t)(base + half) * CD))[q];
    float4 nmx = ((const float4*)(mctx + (size_t)(base + half) * CD))[q];
    float cmax = -1e30f;

    #pragma unroll 1
    for (int pp = 0; pp < 4; pp++) {
        float out4[4];
        #pragma unroll
        for (int p2 = 0; p2 < 2; p2++) {
            int p = 2 * pp + p2;
            int c0 = base + 2 * p;
            s_mp[w][half][q] = nmp;
            s_mx[w][half][q] = nmx;
            __syncwarp();
            if (p < 7) {
                nmp = ((const float4*)(g_mpart + (size_t)(c0 + 2 + half) * CD))[q];
                nmx = ((const float4*)(mctx + (size_t)(c0 + 2 + half) * CD))[q];
            }
            #pragma unroll
            for (int r = 0; r < 2; r++) {
                int c = c0 + r;
                float ac0 = 0.f, ac1 = 0.f, ac2 = 0.f, ac3 = 0.f;
                float ax0 = 0.f, ax1 = 0.f, ax2 = 0.f, ax3 = 0.f;
                #pragma unroll
                for (int i = 0; i < 16; i++) {
                    float4 mp = s_mp[w][r][i];
                    float4 mx = s_mx[w][r][i];
                    float4 w2 = s_w2[i];
                    float t0 = fmaxf(qp[4 * i + 0] + mp.x, 0.0f);
                    float t1 = fmaxf(qp[4 * i + 1] + mp.y, 0.0f);
                    float t2 = fmaxf(qp[4 * i + 2] + mp.z, 0.0f);
                    float t3 = fmaxf(qp[4 * i + 3] + mp.w, 0.0f);
                    ac0 = fmaf(t0, w2.x, ac0);
                    ac1 = fmaf(t1, w2.y, ac1);
                    ac2 = fmaf(t2, w2.z, ac2);
                    ac3 = fmaf(t3, w2.w, ac3);
                    ax0 = fmaf(qn[4 * i + 0], mx.x, ax0);
                    ax1 = fmaf(qn[4 * i + 1], mx.y, ax1);
                    ax2 = fmaf(qn[4 * i + 2], mx.z, ax2);
                    ax3 = fmaf(qn[4 * i + 3], mx.w, ax3);
                }
                float z   = (ac0 + ac1) + (ac2 + ac3) + b2v;
                float ctx = ((ax0 + ax1) + (ax2 + ax3)) * g_invnorm[c];
                float sig = 1.0f / (1.0f + expf(-z));
                float score = 0.5f * sig + 0.3f * ctx + 0.2f * fresh[c];
                out4[2 * p2 + r] = score;
                cmax = fmaxf(cmax, score);
            }
            __syncwarp();
        }
        *(float4*)&g_scores[(size_t)lane * CAP + base + 4 * pp] =
            make_float4(out4[0], out4[1], out4[2], out4[3]);
    }
    g_cmax[lane * NCHUNK + wg] = cmax;
}

// ---------------- K3: top-16 via 3-level REDUX argmax + gather ----------------
__device__ __forceinline__ unsigned ordf(float f) {
    unsigned u = __float_as_uint(f);
    return u ^ ((unsigned)((int)u >> 31) | 0x80000000u);
}

__global__ __launch_bounds__(256) void k3_topk(
    const float* __restrict__ mc, const float* __restrict__ fresh,
    float* __restrict__ out)
{
    __shared__ unsigned s_cmax[NCHUNK];
    __shared__ int   s_sel[TOPK];
    __shared__ float s_val[TOPK];

    int b = blockIdx.x;
    int tid = threadIdx.x;

    for (int i = tid; i < NCHUNK; i += 256)
        s_cmax[i] = ordf(g_cmax[b * NCHUNK + i]);
    __syncthreads();

    if (tid < 32) {
        int lane = tid;
        const float* sc = g_scores + (size_t)b * CAP;
        // 64 supers of 32 chunks; lane owns supers 2*lane, 2*lane+1
        unsigned sv0 = 0u, sv1 = 0u;
        #pragma unroll 8
        for (int j = 0; j < 32; j++) sv0 = max(sv0, s_cmax[(2 * lane) * 32 + j]);
        #pragma unroll 8
        for (int j = 0; j < 32; j++) sv1 = max(sv1, s_cmax[(2 * lane + 1) * 32 + j]);

        for (int k = 0; k < TOPK; k++) {
            // L1: best super (tie -> lowest index)
            unsigned bk; int bs;
            if (sv1 > sv0) { bk = sv1; bs = 2 * lane + 1; }
            else           { bk = sv0; bs = 2 * lane; }
            unsigned m1 = __reduce_max_sync(0xFFFFFFFFu, bk);
            unsigned bl1 = __ballot_sync(0xFFFFFFFFu, bk == m1);
            int S = __shfl_sync(0xFFFFFFFFu, bs, __ffs(bl1) - 1);
            // L2: best chunk within super
            unsigned cm = s_cmax[S * 32 + lane];
            unsigned m2 = __reduce_max_sync(0xFFFFFFFFu, cm);
            unsigned bl2 = __ballot_sync(0xFFFFFFFFu, cm == m2);
            int cl = __ffs(bl2) - 1;
            int C = S * 32 + cl;
            // L3: best element within chunk (rescan 16 scores, mask selected)
            int gbase = C * 16;
            float v = (lane < 16) ? sc[gbase + lane] : -1e38f;
            #pragma unroll
            for (int j = 0; j < TOPK; j++)
                if (j < k && gbase + lane == s_sel[j]) v = -1e38f;
            unsigned key = ordf(v);
            unsigned m3 = __reduce_max_sync(0xFFFFFFFFu, key);
            unsigned bl3 = __ballot_sync(0xFFFFFFFFu, key == m3);
            int el = __ffs(bl3) - 1;
            float ev = __shfl_sync(0xFFFFFFFFu, v, el);
            // update chunk max (exclude selected) and super max
            unsigned key2 = (lane == el) ? 0u : ((lane < 16) ? key : 0u);
            unsigned ncm = __reduce_max_sync(0xFFFFFFFFu, key2);
            unsigned cm2 = (lane == cl) ? ncm : cm;
            unsigned nsm = __reduce_max_sync(0xFFFFFFFFu, cm2);
            if (lane == 0) { s_sel[k] = gbase + el; s_val[k] = ev; s_cmax[C] = ncm; }
            if (lane == (S >> 1)) { if (S & 1) sv1 = nsm; else sv0 = nsm; }
            __syncwarp();
        }
    }
    __syncthreads();

    for (int i = tid; i < TOPK * CD; i += 256) {
        int k = i >> 6, h = i & 63;
        out[(size_t)b * (TOPK * CD) + i] = mc[(size_t)s_sel[k] * CD + h];
    }
    if (tid < TOPK) {
        out[NB * TOPK * CD + b * TOPK + tid] = s_val[tid];
        out[NB * TOPK * CD + NB * TOPK + b * TOPK + tid] = fresh[s_sel[tid]];
    }
}

// ---------------- launch ----------------
extern "C" void kernel_launch(void* const* d_in, const int* in_sizes, int n_in,
                              void* d_out, int out_size)
{
    const float* qc    = (const float*)d_in[0];
    const float* qctx  = (const float*)d_in[1];
    const float* mc    = (const float*)d_in[2];
    const float* mctx  = (const float*)d_in[3];
    const float* fresh = (const float*)d_in[4];
    const float* W1    = (const float*)d_in[5];
    const float* b1    = (const float*)d_in[6];
    const float* W2    = (const float*)d_in[7];
    const float* b2    = (const float*)d_in[8];
    float* out = (float*)d_out;

    k0_prep<<<1, 256>>>(qc, qctx, W1, b1);
    k1_mpart<<<CAP / 128, 256>>>(mc, mctx, W1);
    k2_score<<<CAP / (16 * 8), 256>>>(mctx, fresh, W2, b2);
    k3_topk<<<NB, 256>>>(mc, fresh, out);
}

// round 4
// speedup vs baseline: 1.3563x; 1.1923x over previous
#include <cuda_runtime.h>
#include <math.h>

#define CAP 32768
#define NB  32
#define CD  64
#define TOPK 16
#define NCHUNK 2048   // CAP/16 chunks of 16 per query row
#define FULLM 0xFFFFFFFFu

// ---------------- scratch (no allocations allowed) ----------------
__device__ float g_qpart[NB * CD];        // q@W1[:64] + b1, [b][h]
__device__ float g_qn[NB * CD];           // normalized query_context, [b][h]
__device__ float g_mpart[CAP * CD];       // memory_content @ W1[64:], [c][h]
__device__ float g_invnorm[CAP];          // 1/max(||mctx[c]||, eps)
__device__ float g_scores[NB * CAP];      // final scores, [b][c]
__device__ float g_cmax[NB * NCHUNK];     // per-16-chunk maxes, [b][chunk]

__device__ __forceinline__ unsigned ordf(float f) {
    unsigned u = __float_as_uint(f);
    return u ^ ((unsigned)((int)u >> 31) | 0x80000000u);
}
__device__ __forceinline__ float unordf(unsigned k) {
    unsigned u = (k & 0x80000000u) ? (k ^ 0x80000000u) : ~k;
    return __uint_as_float(u);
}

// ---------------- K1: query prep (block 0) + m_part GEMM + mctx inv-norms ----------------
__global__ __launch_bounds__(256) void k1_mpart(
    const float* __restrict__ mc, const float* __restrict__ mctx,
    const float* __restrict__ W1,
    const float* __restrict__ qc, const float* __restrict__ qctx,
    const float* __restrict__ b1)
{
    __shared__ float sA[128 * 64];
    __shared__ float sB[64 * 64];
    int tid = threadIdx.x;
    int rowbase = blockIdx.x * 128;

    {
        const float4* src = (const float4*)(W1 + 64 * 64);
        float4* dst = (float4*)sB;
        for (int i = tid; i < 1024; i += 256) dst[i] = src[i];
    }
    {
        const float4* src = (const float4*)(mc + (size_t)rowbase * CD);
        float4* dst = (float4*)sA;
        for (int i = tid; i < 2048; i += 256) dst[i] = src[i];
    }
    // mctx inv-norms
    {
        int w = tid >> 5, lane = tid & 31;
        for (int j = 0; j < 16; j++) {
            int c = rowbase + w * 16 + j;
            float v0 = mctx[c * CD + lane];
            float v1 = mctx[c * CD + 32 + lane];
            float ss = v0 * v0 + v1 * v1;
            #pragma unroll
            for (int o = 16; o; o >>= 1) ss += __shfl_xor_sync(FULLM, ss, o);
            if (lane == 0) g_invnorm[c] = 1.0f / fmaxf(sqrtf(ss), 1e-8f);
        }
    }
    // block 0 additionally does the query-side prep (formerly k0)
    if (blockIdx.x == 0) {
        for (int idx = tid; idx < NB * CD; idx += 256) {
            int b = idx >> 6, h = idx & 63;
            float s = b1[h];
            #pragma unroll 8
            for (int d = 0; d < CD; d++)
                s = fmaf(qc[b * CD + d], W1[d * CD + h], s);
            g_qpart[idx] = s;
        }
        int w = tid >> 5, lane = tid & 31;
        for (int j = 0; j < 4; j++) {
            int b = w + j * 8;
            float v0 = qctx[b * CD + lane];
            float v1 = qctx[b * CD + 32 + lane];
            float ss = v0 * v0 + v1 * v1;
            #pragma unroll
            for (int o = 16; o; o >>= 1) ss += __shfl_xor_sync(FULLM, ss, o);
            float inv = 1.0f / fmaxf(sqrtf(ss), 1e-8f);
            g_qn[b * CD + lane]      = v0 * inv;
            g_qn[b * CD + 32 + lane] = v1 * inv;
        }
    }
    __syncthreads();

    int r0 = (tid >> 4) * 8;
    int c0 = (tid & 15) * 4;
    float acc[8][4];
    #pragma unroll
    for (int i = 0; i < 8; i++)
        #pragma unroll
        for (int j = 0; j < 4; j++) acc[i][j] = 0.0f;

    #pragma unroll 2
    for (int d4 = 0; d4 < 16; d4++) {
        float4 bv0 = *(const float4*)&sB[(4 * d4 + 0) * 64 + c0];
        float4 bv1 = *(const float4*)&sB[(4 * d4 + 1) * 64 + c0];
        float4 bv2 = *(const float4*)&sB[(4 * d4 + 2) * 64 + c0];
        float4 bv3 = *(const float4*)&sB[(4 * d4 + 3) * 64 + c0];
        #pragma unroll
        for (int i = 0; i < 8; i++) {
            float4 a = *(const float4*)&sA[(r0 + i) * 64 + 4 * d4];
            acc[i][0] = fmaf(a.x, bv0.x, acc[i][0]);
            acc[i][1] = fmaf(a.x, bv0.y, acc[i][1]);
            acc[i][2] = fmaf(a.x, bv0.z, acc[i][2]);
            acc[i][3] = fmaf(a.x, bv0.w, acc[i][3]);
            acc[i][0] = fmaf(a.y, bv1.x, acc[i][0]);
            acc[i][1] = fmaf(a.y, bv1.y, acc[i][1]);
            acc[i][2] = fmaf(a.y, bv1.z, acc[i][2]);
            acc[i][3] = fmaf(a.y, bv1.w, acc[i][3]);
            acc[i][0] = fmaf(a.z, bv2.x, acc[i][0]);
            acc[i][1] = fmaf(a.z, bv2.y, acc[i][1]);
            acc[i][2] = fmaf(a.z, bv2.z, acc[i][2]);
            acc[i][3] = fmaf(a.z, bv2.w, acc[i][3]);
            acc[i][0] = fmaf(a.w, bv3.x, acc[i][0]);
            acc[i][1] = fmaf(a.w, bv3.y, acc[i][1]);
            acc[i][2] = fmaf(a.w, bv3.z, acc[i][2]);
            acc[i][3] = fmaf(a.w, bv3.w, acc[i][3]);
        }
    }
    #pragma unroll
    for (int i = 0; i < 8; i++) {
        float4 o = make_float4(acc[i][0], acc[i][1], acc[i][2], acc[i][3]);
        *(float4*)&g_mpart[(size_t)(rowbase + r0 + i) * CD + c0] = o;
    }
}

// ---------------- K2: scoring (hot kernel) ----------------
__global__ __launch_bounds__(256, 1) void k2_score(
    const float* __restrict__ mctx, const float* __restrict__ fresh,
    const float* __restrict__ W2, const float* __restrict__ b2p)
{
    __shared__ float4 s_mp[8][2][16];
    __shared__ float4 s_mx[8][2][16];
    __shared__ float4 s_w2[16];

    int tid = threadIdx.x, w = tid >> 5, lane = tid & 31;
    if (tid < 16) s_w2[tid] = ((const float4*)W2)[tid];
    __syncthreads();

    float b2v = b2p[0];

    float qp[64], qn[64];
    {
        const float4* a4 = (const float4*)(g_qpart + lane * CD);
        const float4* n4 = (const float4*)(g_qn + lane * CD);
        #pragma unroll
        for (int i = 0; i < 16; i++) {
            float4 a = a4[i];
            qp[4 * i + 0] = a.x; qp[4 * i + 1] = a.y; qp[4 * i + 2] = a.z; qp[4 * i + 3] = a.w;
            float4 n = n4[i];
            qn[4 * i + 0] = n.x; qn[4 * i + 1] = n.y; qn[4 * i + 2] = n.z; qn[4 * i + 3] = n.w;
        }
    }

    int wg = blockIdx.x * 8 + w;
    int base = wg * 16;
    int half = lane >> 4, q = lane & 15;

    float4 nmp = ((const float4*)(g_mpart + (size_t)(base + half) * CD))[q];
    float4 nmx = ((const float4*)(mctx + (size_t)(base + half) * CD))[q];
    float cmax = -1e30f;

    #pragma unroll 1
    for (int pp = 0; pp < 4; pp++) {
        float out4[4];
        #pragma unroll
        for (int p2 = 0; p2 < 2; p2++) {
            int p = 2 * pp + p2;
            int c0 = base + 2 * p;
            s_mp[w][half][q] = nmp;
            s_mx[w][half][q] = nmx;
            __syncwarp();
            if (p < 7) {
                nmp = ((const float4*)(g_mpart + (size_t)(c0 + 2 + half) * CD))[q];
                nmx = ((const float4*)(mctx + (size_t)(c0 + 2 + half) * CD))[q];
            }
            #pragma unroll
            for (int r = 0; r < 2; r++) {
                int c = c0 + r;
                float ac0 = 0.f, ac1 = 0.f, ac2 = 0.f, ac3 = 0.f;
                float ax0 = 0.f, ax1 = 0.f, ax2 = 0.f, ax3 = 0.f;
                #pragma unroll
                for (int i = 0; i < 16; i++) {
                    float4 mp = s_mp[w][r][i];
                    float4 mx = s_mx[w][r][i];
                    float4 w2 = s_w2[i];
                    float t0 = fmaxf(qp[4 * i + 0] + mp.x, 0.0f);
                    float t1 = fmaxf(qp[4 * i + 1] + mp.y, 0.0f);
                    float t2 = fmaxf(qp[4 * i + 2] + mp.z, 0.0f);
                    float t3 = fmaxf(qp[4 * i + 3] + mp.w, 0.0f);
                    ac0 = fmaf(t0, w2.x, ac0);
                    ac1 = fmaf(t1, w2.y, ac1);
                    ac2 = fmaf(t2, w2.z, ac2);
                    ac3 = fmaf(t3, w2.w, ac3);
                    ax0 = fmaf(qn[4 * i + 0], mx.x, ax0);
                    ax1 = fmaf(qn[4 * i + 1], mx.y, ax1);
                    ax2 = fmaf(qn[4 * i + 2], mx.z, ax2);
                    ax3 = fmaf(qn[4 * i + 3], mx.w, ax3);
                }
                float z   = (ac0 + ac1) + (ac2 + ac3) + b2v;
                float ctx = ((ax0 + ax1) + (ax2 + ax3)) * g_invnorm[c];
                float sig = 1.0f / (1.0f + __expf(-z));
                float score = 0.5f * sig + 0.3f * ctx + 0.2f * fresh[c];
                out4[2 * p2 + r] = score;
                cmax = fmaxf(cmax, score);
            }
            __syncwarp();
        }
        *(float4*)&g_scores[(size_t)lane * CAP + base + 4 * pp] =
            make_float4(out4[0], out4[1], out4[2], out4[3]);
    }
    g_cmax[lane * NCHUNK + wg] = cmax;
}

// ---------------- K3: threshold-filter top-16 + gather ----------------
__global__ __launch_bounds__(256) void k3_topk(
    const float* __restrict__ mc, const float* __restrict__ fresh,
    float* __restrict__ out)
{
    __shared__ unsigned s_key[NCHUNK];    // ordf chunk maxes
    __shared__ unsigned s_tm[256];        // per-thread maxes
    __shared__ unsigned s_tau;
    __shared__ int s_cnt, s_cnt2;
    __shared__ int s_cand[64];            // candidate chunk ids
    __shared__ unsigned s_ekey[64];       // candidate element keys
    __shared__ int s_eidx[64];            // candidate element global indices
    __shared__ int s_sel[TOPK];
    __shared__ float s_val[TOPK];

    int b = blockIdx.x;
    int tid = threadIdx.x;
    int lane = tid & 31;

    // 1. load chunk maxes, per-thread max over 8 chunks
    unsigned tmax = 0;
    #pragma unroll
    for (int j = 0; j < 8; j++) {
        unsigned k = ordf(g_cmax[b * NCHUNK + tid * 8 + j]);
        s_key[tid * 8 + j] = k;
        tmax = max(tmax, k);
    }
    s_tm[tid] = tmax;
    if (tid == 0) { s_cnt = 0; s_cnt2 = 0; }
    if (tid < 64) s_ekey[tid] = 0u;
    __syncthreads();

    // 2. warp 0: tau = 16th largest of 32 group maxes (groups of 64 chunks)
    if (tid < 32) {
        unsigned gm = 0;
        #pragma unroll
        for (int j = 0; j < 8; j++) gm = max(gm, s_tm[lane * 8 + j]);
        int rank = 0;
        #pragma unroll
        for (int j = 0; j < 32; j++) {
            unsigned vj = __shfl_sync(FULLM, gm, j);
            rank += (vj > gm) || (vj == gm && j < lane);
        }
        unsigned eq = __ballot_sync(FULLM, rank == 15);
        unsigned tau = __shfl_sync(FULLM, gm, __ffs(eq) - 1);
        if (lane == 0) s_tau = tau;
    }
    __syncthreads();
    unsigned tau = s_tau;

    // 3. compact candidate chunks (cmax >= tau); guaranteed >= 16, expected ~22
    #pragma unroll
    for (int j = 0; j < 8; j++) {
        int ch = tid * 8 + j;
        if (s_key[ch] >= tau) {
            int p = atomicAdd(&s_cnt, 1);
            if (p < 64) s_cand[p] = ch;
        }
    }
    __syncthreads();
    int cnt = min(s_cnt, 64);

    // 4. load candidate chunks' scores, keep elements with key >= tau
    for (int i = tid; i < cnt * 16; i += 256) {
        int ch = s_cand[i >> 4];
        int gi = ch * 16 + (i & 15);
        unsigned key = ordf(g_scores[(size_t)b * CAP + gi]);
        if (key >= tau) {
            int p = atomicAdd(&s_cnt2, 1);
            if (p < 64) { s_ekey[p] = key; s_eidx[p] = gi; }
        }
    }
    __syncthreads();

    // 5. warp 0: serial top-16 over <=64 smem candidates (no global loads)
    if (tid < 32) {
        for (int k = 0; k < TOPK; k++) {
            unsigned lkey = 0; int lidx = 0x7FFFFFFF; int lpos = -1;
            #pragma unroll
            for (int j = 0; j < 2; j++) {
                int p = lane + 32 * j;
                unsigned kk = s_ekey[p];
                int ii = s_eidx[p];
                if (kk > lkey || (kk == lkey && kk != 0u && ii < lidx)) {
                    lkey = kk; lidx = ii; lpos = p;
                }
            }
            unsigned m = __reduce_max_sync(FULLM, lkey);
            int cand = (lkey == m) ? lidx : 0x7FFFFFFF;
            int gi = __reduce_min_sync(FULLM, cand);
            if (lane == 0) { s_sel[k] = gi; s_val[k] = unordf(m); }
            if (lkey == m && lidx == gi) s_ekey[lpos] = 0u;
            __syncwarp();
        }
    }
    __syncthreads();

    // 6. gather outputs
    for (int i = tid; i < TOPK * CD; i += 256) {
        int k = i >> 6, h = i & 63;
        out[(size_t)b * (TOPK * CD) + i] = mc[(size_t)s_sel[k] * CD + h];
    }
    if (tid < TOPK) {
        out[NB * TOPK * CD + b * TOPK + tid] = s_val[tid];
        out[NB * TOPK * CD + NB * TOPK + b * TOPK + tid] = fresh[s_sel[tid]];
    }
}

// ---------------- launch ----------------
extern "C" void kernel_launch(void* const* d_in, const int* in_sizes, int n_in,
                              void* d_out, int out_size)
{
    const float* qc    = (const float*)d_in[0];
    const float* qctx  = (const float*)d_in[1];
    const float* mc    = (const float*)d_in[2];
    const float* mctx  = (const float*)d_in[3];
    const float* fresh = (const float*)d_in[4];
    const float* W1    = (const float*)d_in[5];
    const float* b1    = (const float*)d_in[6];
    const float* W2    = (const float*)d_in[7];
    const float* b2    = (const float*)d_in[8];
    float* out = (float*)d_out;

    k1_mpart<<<CAP / 128, 256>>>(mc, mctx, W1, qc, qctx, b1);
    k2_score<<<CAP / (16 * 8), 256>>>(mctx, fresh, W2, b2);
    k3_topk<<<NB, 256>>>(mc, fresh, out);
}

// round 5
// speedup vs baseline: 1.4039x; 1.0351x over previous
#include <cuda_runtime.h>
#include <math.h>

#define CAP 32768
#define NB  32
#define CD  64
#define TOPK 16
#define NCHUNK 2048   // CAP/16 chunks of 16 rows
#define FULLM 0xFFFFFFFFu
#define ROWPAD 68     // 16-row tile row pitch in floats (16B pad kills bank conflicts)

// ---------------- scratch (no allocations allowed) ----------------
__device__ float g_qpart[NB * CD];        // q@W1[:64] + b1, [b][h]
__device__ float g_qn[NB * CD];           // normalized query_context, [b][h]
__device__ float g_scores[NB * CAP];      // final scores, [b][c]
__device__ float g_cmax[NB * NCHUNK];     // per-16-chunk maxes, [b][chunk]

__device__ __forceinline__ unsigned ordf(float f) {
    unsigned u = __float_as_uint(f);
    return u ^ ((unsigned)((int)u >> 31) | 0x80000000u);
}
__device__ __forceinline__ float unordf(unsigned k) {
    unsigned u = (k & 0x80000000u) ? (k ^ 0x80000000u) : ~k;
    return __uint_as_float(u);
}

// ---------------- K0: query-side prep (tiny) ----------------
__global__ __launch_bounds__(256) void k0_prep(
    const float* __restrict__ qc, const float* __restrict__ qctx,
    const float* __restrict__ W1, const float* __restrict__ b1)
{
    int tid = threadIdx.x;
    for (int idx = tid; idx < NB * CD; idx += 256) {
        int b = idx >> 6, h = idx & 63;
        float s = b1[h];
        #pragma unroll 8
        for (int d = 0; d < CD; d++)
            s = fmaf(qc[b * CD + d], W1[d * CD + h], s);
        g_qpart[idx] = s;
    }
    int w = tid >> 5, lane = tid & 31;
    for (int j = 0; j < 4; j++) {
        int b = w + j * 8;
        float v0 = qctx[b * CD + lane];
        float v1 = qctx[b * CD + 32 + lane];
        float ss = v0 * v0 + v1 * v1;
        #pragma unroll
        for (int o = 16; o; o >>= 1) ss += __shfl_xor_sync(FULLM, ss, o);
        float inv = 1.0f / fmaxf(sqrtf(ss), 1e-8f);
        g_qn[b * CD + lane]      = v0 * inv;
        g_qn[b * CD + 32 + lane] = v1 * inv;
    }
}

// ---------------- K2: fused m_part GEMM + scoring ----------------
// block = 128 threads (4 warps); warp owns 2 chunks of 16 memory rows.
// lane = query index b throughout scoring.
__global__ __launch_bounds__(128, 1) void k2_fused(
    const float* __restrict__ mc, const float* __restrict__ mctx,
    const float* __restrict__ fresh,
    const float* __restrict__ W1, const float* __restrict__ W2,
    const float* __restrict__ b2p)
{
    __shared__ float  sB[64 * 64];            // W1 bottom half [d][h]
    __shared__ float  sA[4][16 * ROWPAD];     // per-warp: mc rows, then m_part
    __shared__ float4 s_mx[4][2][16];         // per-warp mctx staging (2 rows)
    __shared__ float4 s_w2[16];
    __shared__ float  s_inv[4][2];

    int tid = threadIdx.x, w = tid >> 5, lane = tid & 31;

    // load W1 bottom half + W2
    {
        const float4* src = (const float4*)(W1 + 64 * 64);
        float4* dst = (float4*)sB;
        for (int i = tid; i < 1024; i += 128) dst[i] = src[i];
    }
    if (tid < 16) s_w2[tid] = ((const float4*)W2)[tid];
    __syncthreads();

    float b2v = b2p[0];

    // per-lane query vectors in registers
    float qp[64], qn[64];
    {
        const float4* a4 = (const float4*)(g_qpart + lane * CD);
        const float4* n4 = (const float4*)(g_qn + lane * CD);
        #pragma unroll
        for (int i = 0; i < 16; i++) {
            float4 a = a4[i];
            qp[4 * i + 0] = a.x; qp[4 * i + 1] = a.y; qp[4 * i + 2] = a.z; qp[4 * i + 3] = a.w;
            float4 n = n4[i];
            qn[4 * i + 0] = n.x; qn[4 * i + 1] = n.y; qn[4 * i + 2] = n.z; qn[4 * i + 3] = n.w;
        }
    }

    int rg = lane >> 3;          // GEMM row-group (4 rows each)
    int hg = lane & 7;           // GEMM col-group (8 cols each)
    int half = lane >> 4, q = lane & 15;

    #pragma unroll 1
    for (int it = 0; it < 2; it++) {
        int chunk = blockIdx.x * 8 + w * 2 + it;
        int base = chunk * 16;

        __syncwarp();
        // ---- stage mc rows [16][64] into sA (coalesced) ----
        {
            const float4* mcp = (const float4*)(mc + (size_t)base * CD);
            #pragma unroll
            for (int j = 0; j < 8; j++) {
                int idx = lane + 32 * j;
                int r = idx >> 4, cc = idx & 15;
                *(float4*)&sA[w][r * ROWPAD + cc * 4] = mcp[idx];
            }
        }
        __syncwarp();

        // ---- GEMM: m_part[r][h] = sum_d mc[r][d] * W1b[d][h] ----
        float acc[4][8];
        #pragma unroll
        for (int r = 0; r < 4; r++)
            #pragma unroll
            for (int j = 0; j < 8; j++) acc[r][j] = 0.0f;

        #pragma unroll 4
        for (int d4 = 0; d4 < 16; d4++) {
            float4 a[4];
            #pragma unroll
            for (int r = 0; r < 4; r++)
                a[r] = *(const float4*)&sA[w][(rg * 4 + r) * ROWPAD + d4 * 4];
            #pragma unroll
            for (int k = 0; k < 4; k++) {
                int d = 4 * d4 + k;
                float4 blo = *(const float4*)&sB[d * 64 + hg * 8];
                float4 bhi = *(const float4*)&sB[d * 64 + hg * 8 + 4];
                #pragma unroll
                for (int r = 0; r < 4; r++) {
                    float av = (k == 0) ? a[r].x : (k == 1) ? a[r].y : (k == 2) ? a[r].z : a[r].w;
                    acc[r][0] = fmaf(av, blo.x, acc[r][0]);
                    acc[r][1] = fmaf(av, blo.y, acc[r][1]);
                    acc[r][2] = fmaf(av, blo.z, acc[r][2]);
                    acc[r][3] = fmaf(av, blo.w, acc[r][3]);
                    acc[r][4] = fmaf(av, bhi.x, acc[r][4]);
                    acc[r][5] = fmaf(av, bhi.y, acc[r][5]);
                    acc[r][6] = fmaf(av, bhi.z, acc[r][6]);
                    acc[r][7] = fmaf(av, bhi.w, acc[r][7]);
                }
            }
        }
        __syncwarp();
        // overwrite sA with m_part [r][h]
        #pragma unroll
        for (int r = 0; r < 4; r++) {
            *(float4*)&sA[w][(rg * 4 + r) * ROWPAD + hg * 8] =
                make_float4(acc[r][0], acc[r][1], acc[r][2], acc[r][3]);
            *(float4*)&sA[w][(rg * 4 + r) * ROWPAD + hg * 8 + 4] =
                make_float4(acc[r][4], acc[r][5], acc[r][6], acc[r][7]);
        }
        __syncwarp();

        // ---- scoring: 16 rows, 2 at a time; lane = query b ----
        float4 nmx = ((const float4*)(mctx + (size_t)(base + half) * CD))[q];
        float cmax = -1e30f;

        #pragma unroll 1
        for (int pp = 0; pp < 4; pp++) {
            float out4[4];
            #pragma unroll
            for (int p2 = 0; p2 < 2; p2++) {
                int p = 2 * pp + p2;
                int c0 = base + 2 * p;
                s_mx[w][half][q] = nmx;
                // inline inv-norm for row c0+half (reduce over the 16 q-lanes)
                float ss = nmx.x * nmx.x + nmx.y * nmx.y + nmx.z * nmx.z + nmx.w * nmx.w;
                ss += __shfl_xor_sync(FULLM, ss, 1);
                ss += __shfl_xor_sync(FULLM, ss, 2);
                ss += __shfl_xor_sync(FULLM, ss, 4);
                ss += __shfl_xor_sync(FULLM, ss, 8);
                if (q == 0) s_inv[w][half] = 1.0f / fmaxf(sqrtf(ss), 1e-8f);
                __syncwarp();
                if (p < 7)
                    nmx = ((const float4*)(mctx + (size_t)(c0 + 2 + half) * CD))[q];
                #pragma unroll
                for (int r = 0; r < 2; r++) {
                    int c = c0 + r;
                    int rl = 2 * p + r;   // row-local index in chunk
                    float ac0 = 0.f, ac1 = 0.f, ac2 = 0.f, ac3 = 0.f;
                    float ax0 = 0.f, ax1 = 0.f, ax2 = 0.f, ax3 = 0.f;
                    #pragma unroll
                    for (int i = 0; i < 16; i++) {
                        float4 mp = *(const float4*)&sA[w][rl * ROWPAD + 4 * i];
                        float4 mx = s_mx[w][r][i];
                        float4 w2 = s_w2[i];
                        float t0 = fmaxf(qp[4 * i + 0] + mp.x, 0.0f);
                        float t1 = fmaxf(qp[4 * i + 1] + mp.y, 0.0f);
                        float t2 = fmaxf(qp[4 * i + 2] + mp.z, 0.0f);
                        float t3 = fmaxf(qp[4 * i + 3] + mp.w, 0.0f);
                        ac0 = fmaf(t0, w2.x, ac0);
                        ac1 = fmaf(t1, w2.y, ac1);
                        ac2 = fmaf(t2, w2.z, ac2);
                        ac3 = fmaf(t3, w2.w, ac3);
                        ax0 = fmaf(qn[4 * i + 0], mx.x, ax0);
                        ax1 = fmaf(qn[4 * i + 1], mx.y, ax1);
                        ax2 = fmaf(qn[4 * i + 2], mx.z, ax2);
                        ax3 = fmaf(qn[4 * i + 3], mx.w, ax3);
                    }
                    float z   = (ac0 + ac1) + (ac2 + ac3) + b2v;
                    float ctx = ((ax0 + ax1) + (ax2 + ax3)) * s_inv[w][r];
                    float sig = 1.0f / (1.0f + __expf(-z));
                    float score = 0.5f * sig + 0.3f * ctx + 0.2f * fresh[c];
                    out4[2 * p2 + r] = score;
                    cmax = fmaxf(cmax, score);
                }
                __syncwarp();
            }
            *(float4*)&g_scores[(size_t)lane * CAP + base + 4 * pp] =
                make_float4(out4[0], out4[1], out4[2], out4[3]);
        }
        g_cmax[lane * NCHUNK + chunk] = cmax;
    }
}

// ---------------- K3: threshold-filter top-16 + gather ----------------
__global__ __launch_bounds__(256) void k3_topk(
    const float* __restrict__ mc, const float* __restrict__ fresh,
    float* __restrict__ out)
{
    __shared__ unsigned s_key[NCHUNK];
    __shared__ unsigned s_tm[256];
    __shared__ unsigned s_tau;
    __shared__ int s_cnt, s_cnt2;
    __shared__ int s_cand[64];
    __shared__ unsigned s_ekey[64];
    __shared__ int s_eidx[64];
    __shared__ int s_sel[TOPK];
    __shared__ float s_val[TOPK];

    int b = blockIdx.x;
    int tid = threadIdx.x;
    int lane = tid & 31;

    unsigned tmax = 0;
    #pragma unroll
    for (int j = 0; j < 8; j++) {
        unsigned k = ordf(g_cmax[b * NCHUNK + tid * 8 + j]);
        s_key[tid * 8 + j] = k;
        tmax = max(tmax, k);
    }
    s_tm[tid] = tmax;
    if (tid == 0) { s_cnt = 0; s_cnt2 = 0; }
    if (tid < 64) s_ekey[tid] = 0u;
    __syncthreads();

    if (tid < 32) {
        unsigned gm = 0;
        #pragma unroll
        for (int j = 0; j < 8; j++) gm = max(gm, s_tm[lane * 8 + j]);
        int rank = 0;
        #pragma unroll
        for (int j = 0; j < 32; j++) {
            unsigned vj = __shfl_sync(FULLM, gm, j);
            rank += (vj > gm) || (vj == gm && j < lane);
        }
        unsigned eq = __ballot_sync(FULLM, rank == 15);
        unsigned tau = __shfl_sync(FULLM, gm, __ffs(eq) - 1);
        if (lane == 0) s_tau = tau;
    }
    __syncthreads();
    unsigned tau = s_tau;

    #pragma unroll
    for (int j = 0; j < 8; j++) {
        int ch = tid * 8 + j;
        if (s_key[ch] >= tau) {
            int p = atomicAdd(&s_cnt, 1);
            if (p < 64) s_cand[p] = ch;
        }
    }
    __syncthreads();
    int cnt = min(s_cnt, 64);

    for (int i = tid; i < cnt * 16; i += 256) {
        int ch = s_cand[i >> 4];
        int gi = ch * 16 + (i & 15);
        unsigned key = ordf(g_scores[(size_t)b * CAP + gi]);
        if (key >= tau) {
            int p = atomicAdd(&s_cnt2, 1);
            if (p < 64) { s_ekey[p] = key; s_eidx[p] = gi; }
        }
    }
    __syncthreads();

    if (tid < 32) {
        for (int k = 0; k < TOPK; k++) {
            unsigned lkey = 0; int lidx = 0x7FFFFFFF; int lpos = -1;
            #pragma unroll
            for (int j = 0; j < 2; j++) {
                int p = lane + 32 * j;
                unsigned kk = s_ekey[p];
                int ii = s_eidx[p];
                if (kk > lkey || (kk == lkey && kk != 0u && ii < lidx)) {
                    lkey = kk; lidx = ii; lpos = p;
                }
            }
            unsigned m = __reduce_max_sync(FULLM, lkey);
            int cand = (lkey == m) ? lidx : 0x7FFFFFFF;
            int gi = __reduce_min_sync(FULLM, cand);
            if (lane == 0) { s_sel[k] = gi; s_val[k] = unordf(m); }
            if (lkey == m && lidx == gi) s_ekey[lpos] = 0u;
            __syncwarp();
        }
    }
    __syncthreads();

    for (int i = tid; i < TOPK * CD; i += 256) {
        int k = i >> 6, h = i & 63;
        out[(size_t)b * (TOPK * CD) + i] = mc[(size_t)s_sel[k] * CD + h];
    }
    if (tid < TOPK) {
        out[NB * TOPK * CD + b * TOPK + tid] = s_val[tid];
        out[NB * TOPK * CD + NB * TOPK + b * TOPK + tid] = fresh[s_sel[tid]];
    }
}

// ---------------- launch ----------------
extern "C" void kernel_launch(void* const* d_in, const int* in_sizes, int n_in,
                              void* d_out, int out_size)
{
    const float* qc    = (const float*)d_in[0];
    const float* qctx  = (const float*)d_in[1];
    const float* mc    = (const float*)d_in[2];
    const float* mctx  = (const float*)d_in[3];
    const float* fresh = (const float*)d_in[4];
    const float* W1    = (const float*)d_in[5];
    const float* b1    = (const float*)d_in[6];
    const float* W2    = (const float*)d_in[7];
    const float* b2    = (const float*)d_in[8];
    float* out = (float*)d_out;

    k0_prep<<<1, 256>>>(qc, qctx, W1, b1);
    k2_fused<<<NCHUNK / 8, 128>>>(mc, mctx, fresh, W1, W2, b2);
    k3_topk<<<NB, 256>>>(mc, fresh, out);
}

// round 7
// speedup vs baseline: 1.8525x; 1.3195x over previous
#include <cuda_runtime.h>
#include <math.h>

#define CAP 32768
#define NB  32
#define CD  64
#define TOPK 16
#define NCHUNK 2048
#define FULLM 0xFFFFFFFFu
#define ROWPAD 68

typedef unsigned long long ull;

#define FMA2(d, a, b, c) \
    asm("fma.rn.f32x2 %0, %1, %2, %3;" : "=l"(d) : "l"(a), "l"(b), "l"(c))
#define ADD2(d, a, b) \
    asm("add.rn.f32x2 %0, %1, %2;" : "=l"(d) : "l"(a), "l"(b))
#define PACK2(d, lo, hi) \
    asm("mov.b64 %0, {%1, %2};" : "=l"(d) : "f"(lo), "f"(hi))
#define UNPACK2(lo, hi, x) \
    asm("mov.b64 {%0, %1}, %2;" : "=f"(lo), "=f"(hi) : "l"(x))

// ---------------- scratch ----------------
__device__ float g_qpart[NB * CD];
__device__ float g_qn[NB * CD];
__device__ float g_scores[NB * CAP];
__device__ float g_cmax[NB * NCHUNK];

__device__ __forceinline__ unsigned ordf(float f) {
    unsigned u = __float_as_uint(f);
    return u ^ ((unsigned)((int)u >> 31) | 0x80000000u);
}
__device__ __forceinline__ float unordf(unsigned k) {
    unsigned u = (k & 0x80000000u) ? (k ^ 0x80000000u) : ~k;
    return __uint_as_float(u);
}

// ---------------- K0: query prep, block per query ----------------
__global__ __launch_bounds__(64) void k0_prep(
    const float* __restrict__ qc, const float* __restrict__ qctx,
    const float* __restrict__ W1, const float* __restrict__ b1)
{
    __shared__ float sq[64];
    __shared__ float sps[2];
    int b = blockIdx.x, h = threadIdx.x;
    sq[h] = qc[b * CD + h];
    float v = qctx[b * CD + h];
    __syncthreads();

    float s = b1[h];
    #pragma unroll
    for (int d = 0; d < CD; d++)
        s = fmaf(sq[d], W1[d * CD + h], s);
    g_qpart[b * CD + h] = s;

    float ss = v * v;
    #pragma unroll
    for (int o = 16; o; o >>= 1) ss += __shfl_xor_sync(FULLM, ss, o);
    if ((h & 31) == 0) sps[h >> 5] = ss;
    __syncthreads();
    float inv = 1.0f / fmaxf(sqrtf(sps[0] + sps[1]), 1e-8f);
    g_qn[b * CD + h] = v * inv;
}

// ---------------- K2: fused m_part GEMM + scoring (f32x2 packed) ----------------
__global__ __launch_bounds__(128, 1) void k2_fused(
    const float* __restrict__ mc, const float* __restrict__ mctx,
    const float* __restrict__ fresh,
    const float* __restrict__ W1, const float* __restrict__ W2,
    const float* __restrict__ b2p)
{
    __shared__ float  sB[64 * 64];
    __shared__ float  sA[4][16 * ROWPAD];
    __shared__ float4 s_mx[4][2][16];
    __shared__ float4 s_w2[16];
    __shared__ float  s_inv[4][2];

    int tid = threadIdx.x, w = tid >> 5, lane = tid & 31;

    {
        const float4* src = (const float4*)(W1 + 64 * 64);
        float4* dst = (float4*)sB;
        for (int i = tid; i < 1024; i += 128) dst[i] = src[i];
    }
    if (tid < 16) s_w2[tid] = ((const float4*)W2)[tid];
    __syncthreads();

    float b2v = b2p[0];

    // per-lane query vectors, packed pairs
    ull qp2[32], qn2[32];
    {
        const ulonglong2* a4 = (const ulonglong2*)(g_qpart + lane * CD);
        const ulonglong2* n4 = (const ulonglong2*)(g_qn + lane * CD);
        #pragma unroll
        for (int i = 0; i < 16; i++) {
            ulonglong2 a = a4[i];
            qp2[2 * i] = a.x; qp2[2 * i + 1] = a.y;
            ulonglong2 n = n4[i];
            qn2[2 * i] = n.x; qn2[2 * i + 1] = n.y;
        }
    }

    int rg = lane >> 3;
    int hg = lane & 7;
    int half = lane >> 4, q = lane & 15;

    #pragma unroll 1
    for (int it = 0; it < 2; it++) {
        int chunk = blockIdx.x * 8 + w * 2 + it;
        int base = chunk * 16;

        __syncwarp();
        // stage mc rows [16][64]
        {
            const float4* mcp = (const float4*)(mc + (size_t)base * CD);
            #pragma unroll
            for (int j = 0; j < 8; j++) {
                int idx = lane + 32 * j;
                int r = idx >> 4, cc = idx & 15;
                *(float4*)&sA[w][r * ROWPAD + cc * 4] = mcp[idx];
            }
        }
        __syncwarp();

        // GEMM: m_part[r][h] = sum_d mc[r][d] * W1b[d][h], packed over h
        ull acc2[4][4];
        #pragma unroll
        for (int r = 0; r < 4; r++)
            #pragma unroll
            for (int j = 0; j < 4; j++) acc2[r][j] = 0ull;

        #pragma unroll 4
        for (int d4 = 0; d4 < 16; d4++) {
            float4 a[4];
            #pragma unroll
            for (int r = 0; r < 4; r++)
                a[r] = *(const float4*)&sA[w][(rg * 4 + r) * ROWPAD + d4 * 4];
            #pragma unroll
            for (int k = 0; k < 4; k++) {
                int d = 4 * d4 + k;
                ulonglong2 b01 = *(const ulonglong2*)&sB[d * 64 + hg * 8];
                ulonglong2 b23 = *(const ulonglong2*)&sB[d * 64 + hg * 8 + 4];
                #pragma unroll
                for (int r = 0; r < 4; r++) {
                    float av = (k == 0) ? a[r].x : (k == 1) ? a[r].y : (k == 2) ? a[r].z : a[r].w;
                    ull av2; PACK2(av2, av, av);
                    FMA2(acc2[r][0], av2, b01.x, acc2[r][0]);
                    FMA2(acc2[r][1], av2, b01.y, acc2[r][1]);
                    FMA2(acc2[r][2], av2, b23.x, acc2[r][2]);
                    FMA2(acc2[r][3], av2, b23.y, acc2[r][3]);
                }
            }
        }
        __syncwarp();
        #pragma unroll
        for (int r = 0; r < 4; r++) {
            ulonglong2 lo, hi;
            lo.x = acc2[r][0]; lo.y = acc2[r][1];
            hi.x = acc2[r][2]; hi.y = acc2[r][3];
            *(ulonglong2*)&sA[w][(rg * 4 + r) * ROWPAD + hg * 8] = lo;
            *(ulonglong2*)&sA[w][(rg * 4 + r) * ROWPAD + hg * 8 + 4] = hi;
        }
        __syncwarp();

        // scoring: 16 rows, 2 at a time; lane = query b
        float4 nmx = ((const float4*)(mctx + (size_t)(base + half) * CD))[q];
        float cmax = -1e30f;

        #pragma unroll 1
        for (int pp = 0; pp < 4; pp++) {
            float out4[4];
            #pragma unroll
            for (int p2 = 0; p2 < 2; p2++) {
                int p = 2 * pp + p2;
                int c0 = base + 2 * p;
                s_mx[w][half][q] = nmx;
                float ssn = nmx.x * nmx.x + nmx.y * nmx.y + nmx.z * nmx.z + nmx.w * nmx.w;
                ssn += __shfl_xor_sync(FULLM, ssn, 1);
                ssn += __shfl_xor_sync(FULLM, ssn, 2);
                ssn += __shfl_xor_sync(FULLM, ssn, 4);
                ssn += __shfl_xor_sync(FULLM, ssn, 8);
                if (q == 0) s_inv[w][half] = 1.0f / fmaxf(sqrtf(ssn), 1e-8f);
                __syncwarp();
                if (p < 7)
                    nmx = ((const float4*)(mctx + (size_t)(c0 + 2 + half) * CD))[q];
                #pragma unroll
                for (int r = 0; r < 2; r++) {
                    int c = c0 + r;
                    int rl = 2 * p + r;
                    ull ac01 = 0ull, ac23 = 0ull;   // MLP dot pairs
                    ull ax01 = 0ull, ax23 = 0ull;   // ctx dot pairs
                    #pragma unroll
                    for (int i = 0; i < 16; i++) {
                        ulonglong2 mp = *(const ulonglong2*)&sA[w][rl * ROWPAD + 4 * i];
                        ulonglong2 mx = *(const ulonglong2*)&s_mx[w][r][i];
                        ulonglong2 w2 = *(const ulonglong2*)&s_w2[i];
                        ull t01; ADD2(t01, qp2[2 * i], mp.x);
                        ull t23; ADD2(t23, qp2[2 * i + 1], mp.y);
                        float u0, u1, u2, u3;
                        UNPACK2(u0, u1, t01);
                        UNPACK2(u2, u3, t23);
                        u0 = fmaxf(u0, 0.0f); u1 = fmaxf(u1, 0.0f);
                        u2 = fmaxf(u2, 0.0f); u3 = fmaxf(u3, 0.0f);
                        ull r01, r23;
                        PACK2(r01, u0, u1);
                        PACK2(r23, u2, u3);
                        FMA2(ac01, r01, w2.x, ac01);
                        FMA2(ac23, r23, w2.y, ac23);
                        FMA2(ax01, qn2[2 * i], mx.x, ax01);
                        FMA2(ax23, qn2[2 * i + 1], mx.y, ax23);
                    }
                    float a0, a1, a2, a3, x0, x1, x2, x3;
                    UNPACK2(a0, a1, ac01);
                    UNPACK2(a2, a3, ac23);
                    UNPACK2(x0, x1, ax01);
                    UNPACK2(x2, x3, ax23);
                    float z   = (a0 + a1) + (a2 + a3) + b2v;
                    float ctx = ((x0 + x1) + (x2 + x3)) * s_inv[w][r];
                    float sig = 1.0f / (1.0f + __expf(-z));
                    float score = 0.5f * sig + 0.3f * ctx + 0.2f * fresh[c];
                    out4[2 * p2 + r] = score;
                    cmax = fmaxf(cmax, score);
                }
                __syncwarp();
            }
            *(float4*)&g_scores[(size_t)lane * CAP + base + 4 * pp] =
                make_float4(out4[0], out4[1], out4[2], out4[3]);
        }
        g_cmax[lane * NCHUNK + chunk] = cmax;
    }
}

// ---------------- K3: threshold-filter top-16 + gather ----------------
__global__ __launch_bounds__(256) void k3_topk(
    const float* __restrict__ mc, const float* __restrict__ fresh,
    float* __restrict__ out)
{
    __shared__ unsigned s_key[NCHUNK];
    __shared__ unsigned s_tm[256];
    __shared__ unsigned s_tau;
    __shared__ int s_cnt, s_cnt2;
    __shared__ int s_cand[64];
    __shared__ unsigned s_ekey[64];
    __shared__ int s_eidx[64];
    __shared__ int s_sel[TOPK];
    __shared__ float s_val[TOPK];

    int b = blockIdx.x;
    int tid = threadIdx.x;
    int lane = tid & 31;

    unsigned tmax = 0;
    #pragma unroll
    for (int j = 0; j < 8; j++) {
        unsigned k = ordf(g_cmax[b * NCHUNK + tid * 8 + j]);
        s_key[tid * 8 + j] = k;
        tmax = max(tmax, k);
    }
    s_tm[tid] = tmax;
    if (tid == 0) { s_cnt = 0; s_cnt2 = 0; }
    if (tid < 64) s_ekey[tid] = 0u;
    __syncthreads();

    if (tid < 32) {
        unsigned gm = 0;
        #pragma unroll
        for (int j = 0; j < 8; j++) gm = max(gm, s_tm[lane * 8 + j]);
        int rank = 0;
        #pragma unroll
        for (int j = 0; j < 32; j++) {
            unsigned vj = __shfl_sync(FULLM, gm, j);
            rank += (vj > gm) || (vj == gm && j < lane);
        }
        unsigned eq = __ballot_sync(FULLM, rank == 15);
        unsigned tau = __shfl_sync(FULLM, gm, __ffs(eq) - 1);
        if (lane == 0) s_tau = tau;
    }
    __syncthreads();
    unsigned tau = s_tau;

    #pragma unroll
    for (int j = 0; j < 8; j++) {
        int ch = tid * 8 + j;
        if (s_key[ch] >= tau) {
            int p = atomicAdd(&s_cnt, 1);
            if (p < 64) s_cand[p] = ch;
        }
    }
    __syncthreads();
    int cnt = min(s_cnt, 64);

    for (int i = tid; i < cnt * 16; i += 256) {
        int ch = s_cand[i >> 4];
        int gi = ch * 16 + (i & 15);
        unsigned key = ordf(g_scores[(size_t)b * CAP + gi]);
        if (key >= tau) {
            int p = atomicAdd(&s_cnt2, 1);
            if (p < 64) { s_ekey[p] = key; s_eidx[p] = gi; }
        }
    }
    __syncthreads();

    if (tid < 32) {
        for (int k = 0; k < TOPK; k++) {
            unsigned lkey = 0; int lidx = 0x7FFFFFFF; int lpos = -1;
            #pragma unroll
            for (int j = 0; j < 2; j++) {
                int p = lane + 32 * j;
                unsigned kk = s_ekey[p];
                int ii = s_eidx[p];
                if (kk > lkey || (kk == lkey && kk != 0u && ii < lidx)) {
                    lkey = kk; lidx = ii; lpos = p;
                }
            }
            unsigned m = __reduce_max_sync(FULLM, lkey);
            int cand = (lkey == m) ? lidx : 0x7FFFFFFF;
            int gi = __reduce_min_sync(FULLM, cand);
            if (lane == 0) { s_sel[k] = gi; s_val[k] = unordf(m); }
            if (lkey == m && lidx == gi) s_ekey[lpos] = 0u;
            __syncwarp();
        }
    }
    __syncthreads();

    for (int i = tid; i < TOPK * CD; i += 256) {
        int k = i >> 6, h = i & 63;
        out[(size_t)b * (TOPK * CD) + i] = mc[(size_t)s_sel[k] * CD + h];
    }
    if (tid < TOPK) {
        out[NB * TOPK * CD + b * TOPK + tid] = s_val[tid];
        out[NB * TOPK * CD + NB * TOPK + b * TOPK + tid] = fresh[s_sel[tid]];
    }
}

// ---------------- launch ----------------
extern "C" void kernel_launch(void* const* d_in, const int* in_sizes, int n_in,
                              void* d_out, int out_size)
{
    const float* qc    = (const float*)d_in[0];
    const float* qctx  = (const float*)d_in[1];
    const float* mc    = (const float*)d_in[2];
    const float* mctx  = (const float*)d_in[3];
    const float* fresh = (const float*)d_in[4];
    const float* W1    = (const float*)d_in[5];
    const float* b1    = (const float*)d_in[6];
    const float* W2    = (const float*)d_in[7];
    const float* b2    = (const float*)d_in[8];
    float* out = (float*)d_out;

    k0_prep<<<NB, 64>>>(qc, qctx, W1, b1);
    k2_fused<<<NCHUNK / 8, 128>>>(mc, mctx, fresh, W1, W2, b2);
    k3_topk<<<NB, 256>>>(mc, fresh, out);
}